// round 13
// baseline (speedup 1.0000x reference)
#include <cuda_runtime.h>
#include <cuda_fp16.h>
#include <cstdint>

constexpr int Bn = 8, Cn = 128, Tn = 32768, Ln = 256;
constexpr float SLOPE = 0.2f;
constexpr int NT = 1024;

// ---- device scratch ----
__device__ __half gA  [(size_t)Bn * Ln * 3 * Cn * Cn];  // lvc weight [b][l][k][co][ci] fp16
__device__ __half g_h [(size_t)Bn * Cn * Tn];           // LVC output fp16, layout [b][t][co]
__device__ __half gX  [(size_t)Bn * Tn * Cn];           // x fp16, layout [b][t][ci]
__device__ __half gA2 [3 * Cn * Cn];                    // dconv weight [k][co][ci] fp16

// ---- helpers ----
static __device__ __forceinline__ uint32_t smem_u32(const void* p) {
    uint32_t a;
    asm("{ .reg .u64 t; cvta.to.shared.u64 t, %1; cvt.u32.u64 %0, t; }" : "=r"(a) : "l"(p));
    return a;
}
static __device__ __forceinline__ void ldm_x4(uint32_t &r0, uint32_t &r1,
                                              uint32_t &r2, uint32_t &r3, uint32_t addr) {
    asm volatile("ldmatrix.sync.aligned.m8n8.x4.shared.b16 {%0,%1,%2,%3}, [%4];"
                 : "=r"(r0), "=r"(r1), "=r"(r2), "=r"(r3) : "r"(addr));
}
static __device__ __forceinline__ void mma16816(float* c, const uint32_t* a, const uint32_t* b) {
    asm volatile("mma.sync.aligned.m16n8k16.row.col.f32.f16.f16.f32 "
                 "{%0,%1,%2,%3}, {%4,%5,%6,%7}, {%8,%9}, {%0,%1,%2,%3};"
                 : "+f"(c[0]), "+f"(c[1]), "+f"(c[2]), "+f"(c[3])
                 : "r"(a[0]), "r"(a[1]), "r"(a[2]), "r"(a[3]), "r"(b[0]), "r"(b[1]));
}
static __device__ __forceinline__ void cpasync16(uint32_t s, const void* g) {
    asm volatile("cp.async.cg.shared.global [%0], [%1], 16;" :: "r"(s), "l"(g));
}
static __device__ __forceinline__ void cp_commit() {
    asm volatile("cp.async.commit_group;" ::: "memory");
}
static __device__ __forceinline__ void cp_wait0() {
    asm volatile("cp.async.wait_group 0;" ::: "memory");
}
static __device__ __forceinline__ void cp_wait1() {
    asm volatile("cp.async.wait_group 1;" ::: "memory");
}

constexpr uint32_t ATILE = 34816u;          // 128 rows x 272B (one k-tile)

// ---- lvc smem: xT [0, 70176) (258 x 272B); A double-buffer at ABUF; EP at EPOFF ----
constexpr uint32_t ABUF  = 70400u;
constexpr uint32_t EPOFF = ABUF + 2u * ATILE;       // 140032
constexpr uint32_t SMEM_LVC = EPOFF + ATILE;        // 174848

// ---- dconv smem: xT [0, 71264) (262 rows x 272B); A at DSOFF ----
constexpr uint32_t DSOFF = 71264u;
constexpr uint32_t SMEM_DCV = DSOFF + 3u * ATILE;   // 175712

// ---- prep: weight-norm conv weight -> fp16 [k][co][ci] ----
__global__ void wn_prep_kernel(const float* __restrict__ conv_v,
                               const float* __restrict__ conv_g) {
    __shared__ float sc[Cn];
    int co = threadIdx.x;
    float s = 0.f;
    for (int i = 0; i < Cn * 3; ++i) {
        float t = conv_v[co * (Cn * 3) + i];
        s += t * t;
    }
    sc[co] = conv_g[co] / sqrtf(s);
    __syncthreads();
    for (int i = threadIdx.x; i < 3 * Cn * Cn; i += Cn) {
        int k = i >> 14, rest = i & 16383, c2 = rest >> 7, ci = rest & 127;
        gA2[i] = __float2half_rn(conv_v[(c2 * Cn + ci) * 3 + k] * sc[c2]);
    }
}

// ---- transpose W[b][ci][co][k][l] -> gA[b][l][k][co][ci] fp16 (vectorized) ----
__global__ __launch_bounds__(512)
void transpose_w_kernel(const float* __restrict__ W) {
    __shared__ float tile[64][36];
    int z = blockIdx.z;
    int k = z % 3, co = (z / 3) & 127, b = z / (3 * Cn);
    int l0 = blockIdx.x * 32, ci0 = blockIdx.y * 64;
    const int tid = threadIdx.x;
    {
        int cir = tid >> 3, l4 = (tid & 7) * 4;
        float4 v = *(const float4*)(W +
            ((((size_t)b * Cn + ci0 + cir) * Cn + co) * 3 + k) * Ln + l0 + l4);
        *(float4*)&tile[cir][l4] = v;
    }
    __syncthreads();
    {
        int lr = tid >> 4, cig = (tid & 15) * 4;
        __half2 h0 = __floats2half2_rn(tile[cig][lr],     tile[cig + 1][lr]);
        __half2 h1 = __floats2half2_rn(tile[cig + 2][lr], tile[cig + 3][lr]);
        uint2 w;
        w.x = *(uint32_t*)&h0;
        w.y = *(uint32_t*)&h1;
        size_t o = ((((size_t)b * Ln + l0 + lr) * 3 + k) * Cn + co) * Cn + ci0 + cig;
        *(uint2*)(gA + o) = w;
    }
}

// ---- xprep: x fp32 [b][ci][t] -> gX fp16 [b][t][ci] ----
__global__ __launch_bounds__(512)
void xprep_kernel(const float* __restrict__ x, __half* __restrict__ xT) {
    __shared__ float tile[128][36];
    const int b = blockIdx.y;
    const int t0 = blockIdx.x * 32;
    const int tid = threadIdx.x;
    #pragma unroll
    for (int j = 0; j < 2; ++j) {
        int i = tid + j * 512;
        int ci = i >> 3, t4 = (i & 7) * 4;
        *(float4*)&tile[ci][t4] =
            *(const float4*)(x + ((size_t)b * Cn + ci) * Tn + t0 + t4);
    }
    __syncthreads();
    #pragma unroll
    for (int j = 0; j < 2; ++j) {
        int i = tid + j * 512;
        int tr = i >> 5, cig = (i & 31) * 4;
        __half2 h0 = __floats2half2_rn(tile[cig][tr],     tile[cig + 1][tr]);
        __half2 h1 = __floats2half2_rn(tile[cig + 2][tr], tile[cig + 3][tr]);
        uint2 w;
        w.x = *(uint32_t*)&h0;
        w.y = *(uint32_t*)&h1;
        *(uint2*)(xT + ((size_t)b * Tn + t0 + tr) * Cn + cig) = w;
    }
}

// ---- LVC: 256-wide CTA, cp.async window + 2-deep k-pipeline, transposed epilogue ----
__global__ __launch_bounds__(NT, 1)
void lvc_kernel(const __half* __restrict__ xTsrc, const __half* __restrict__ Aw,
                const float* __restrict__ bias, __half* __restrict__ dstT) {
    extern __shared__ char sm[];
    const uint32_t smb = smem_u32(sm);
    const int tid = threadIdx.x;
    const int b = blockIdx.x >> 7, tt = blockIdx.x & 127;
    const int t0 = tt * 256;

    // window: xT rows c in [0,258), t = t0 - 1 + c — direct cp.async of gX rows
    for (int i = tid; i < 258 * 16; i += NT) {
        int row = i >> 4, chunk = i & 15;
        int t = t0 - 1 + row;
        uint32_t d = smb + (uint32_t)row * 272u + (uint32_t)chunk * 16u;
        if (t >= 0 && t < Tn)
            cpasync16(d, xTsrc + ((size_t)b * Tn + t) * 128 + chunk * 8);
        else
            *(uint4*)(sm + (uint32_t)row * 272u + (uint32_t)chunk * 16u) =
                make_uint4(0, 0, 0, 0);
    }
    cp_commit();

    auto stage_kt = [&](int kt) {
        int p = kt / 3, k = kt - 3 * p;
        const uint4* sA = (const uint4*)(Aw +
            ((size_t)(b * Ln + tt * 2 + p) * 3 + k) * 16384);
        uint32_t buf = smb + ABUF + (uint32_t)(kt & 1) * ATILE;
        #pragma unroll
        for (int j = 0; j < 2; ++j) {
            int i = tid + j * NT;
            int co = i >> 4, c8 = (i & 15) << 3;
            cpasync16(buf + (uint32_t)co * 272u + (uint32_t)c8 * 2u, sA + i);
        }
        cp_commit();
    };
    stage_kt(0);
    stage_kt(1);

    const int warp = tid >> 5, lane = tid & 31;
    const int co0 = (warp >> 3) * 32, s0 = (warp & 7) * 16;
    const uint32_t lrow = lane & 15, lcol = (uint32_t)(lane >> 4) << 4;
    const int g = lane >> 2, q = lane & 3;
    const uint32_t arow = (uint32_t)(co0 + (int)lrow) * 272u + lcol;
    __half* ep = (__half*)(sm + EPOFF);

    #pragma unroll
    for (int p = 0; p < 2; ++p) {
        float acc[2][2][4];
        #pragma unroll
        for (int mi = 0; mi < 2; ++mi)
            #pragma unroll
            for (int ni = 0; ni < 2; ++ni)
                #pragma unroll
                for (int qq = 0; qq < 4; ++qq) acc[mi][ni][qq] = 0.f;

        #pragma unroll
        for (int k = 0; k < 3; ++k) {
            const int kt = 3 * p + k;
            if (kt == 5) cp_wait0(); else cp_wait1();
            __syncthreads();

            const uint32_t abase = smb + ABUF + (uint32_t)(kt & 1) * ATILE + arow;
            const uint32_t bbase = smb + (uint32_t)(p * 128 + k + s0 + (int)lrow) * 272u + lcol;
            #pragma unroll
            for (int ch = 0; ch < 8; ++ch) {
                const uint32_t cb = (uint32_t)ch * 32u;
                uint32_t af[2][4];
                #pragma unroll
                for (int mi = 0; mi < 2; ++mi)
                    ldm_x4(af[mi][0], af[mi][1], af[mi][2], af[mi][3],
                           abase + (uint32_t)(mi * 16) * 272u + cb);
                uint32_t r0, r1, r2, r3;
                ldm_x4(r0, r1, r2, r3, bbase + cb);
                uint32_t bf[2][2] = {{r0, r2}, {r1, r3}};
                #pragma unroll
                for (int mi = 0; mi < 2; ++mi)
                    #pragma unroll
                    for (int ni = 0; ni < 2; ++ni)
                        mma16816(acc[mi][ni], af[mi], bf[ni]);
            }
            __syncthreads();
            if (kt < 4) stage_kt(kt + 2);
        }

        // epilogue: bias + leaky -> EP smem [s][co] -> coalesced rows of g_hT
        const int l = tt * 2 + p;
        #pragma unroll
        for (int mi = 0; mi < 2; ++mi)
            #pragma unroll
            for (int h = 0; h < 2; ++h) {
                int co = co0 + mi * 16 + g + h * 8;
                float bv = bias[(size_t)(b * Cn + co) * Ln + l];
                #pragma unroll
                for (int ni = 0; ni < 2; ++ni) {
                    int s = s0 + ni * 8 + q * 2;
                    float v0 = acc[mi][ni][2 * h]     + bv;
                    float v1 = acc[mi][ni][2 * h + 1] + bv;
                    v0 = fmaxf(v0, SLOPE * v0);
                    v1 = fmaxf(v1, SLOPE * v1);
                    ep[(uint32_t)s * 136u + (uint32_t)co]       = __float2half_rn(v0);
                    ep[(uint32_t)(s + 1) * 136u + (uint32_t)co] = __float2half_rn(v1);
                }
            }
        __syncthreads();
        {
            __half* dbase = dstT + ((size_t)b * Tn + t0 + p * 128) * 128;
            #pragma unroll
            for (int j = 0; j < 2; ++j) {
                int i = tid + j * NT;
                int row = i >> 4, chunk = i & 15;
                uint4 v = *(uint4*)(sm + EPOFF + (uint32_t)row * 272u + (uint32_t)chunk * 16u);
                *(uint4*)(dbase + (size_t)row * 128 + chunk * 8) = v;
            }
        }
    }
}

// ---- dconv: R11 verbatim (256-wide, 32x32 warp tiles, pure-cp.async window) ----
__global__ __launch_bounds__(NT, 1)
void dconv_kernel(const __half* __restrict__ srcT, const __half* __restrict__ Aw,
                  const float* __restrict__ conv_b, float* __restrict__ out) {
    extern __shared__ char sm[];
    const uint32_t smb = smem_u32(sm);
    const int tid = threadIdx.x;
    const int b = blockIdx.x >> 7, tt = blockIdx.x & 127;
    const int t0 = tt * 256;

    for (int i = tid; i < 262 * 16; i += NT) {
        int row = i >> 4, chunk = i & 15;
        int t = t0 - 3 + row;
        uint32_t d = smb + (uint32_t)row * 272u + (uint32_t)chunk * 16u;
        if (t >= 0 && t < Tn)
            cpasync16(d, srcT + ((size_t)b * Tn + t) * 128 + chunk * 8);
        else
            *(uint4*)(sm + (uint32_t)row * 272u + (uint32_t)chunk * 16u) =
                make_uint4(0, 0, 0, 0);
    }
    {
        const uint4* sA = (const uint4*)Aw;
        #pragma unroll
        for (int j = 0; j < 6; ++j) {
            int i = tid + j * NT;
            int k = i >> 11, r = i & 2047;
            int co = r >> 4, c8 = (r & 15) << 3;
            cpasync16(smb + DSOFF + (uint32_t)k * ATILE
                      + (uint32_t)co * 272u + (uint32_t)c8 * 2u, sA + i);
        }
    }
    cp_commit();
    cp_wait0();
    __syncthreads();

    const int warp = tid >> 5, lane = tid & 31;
    const int co0 = (warp >> 3) * 32, s0 = (warp & 7) * 32;
    const uint32_t lrow = lane & 15, lcol = (uint32_t)(lane >> 4) << 4;

    uint32_t aoffs[2], boffs[2];
    #pragma unroll
    for (int mi = 0; mi < 2; ++mi)
        aoffs[mi] = smb + DSOFF + (uint32_t)(co0 + mi * 16 + (int)lrow) * 272u + lcol;
    #pragma unroll
    for (int p = 0; p < 2; ++p)
        boffs[p] = smb + (uint32_t)(s0 + p * 16 + (int)lrow) * 272u + lcol;

    float acc[2][4][4];
    #pragma unroll
    for (int mi = 0; mi < 2; ++mi)
        #pragma unroll
        for (int ni = 0; ni < 4; ++ni)
            #pragma unroll
            for (int q = 0; q < 4; ++q) acc[mi][ni][q] = 0.f;

    #pragma unroll
    for (int k = 0; k < 3; ++k) {
        const uint32_t ak = (uint32_t)k * ATILE;
        const uint32_t bk = (uint32_t)(3 * k) * 272u;
        #pragma unroll
        for (int ch = 0; ch < 8; ++ch) {
            const uint32_t cb = (uint32_t)ch * 32u;
            uint32_t af[2][4];
            #pragma unroll
            for (int mi = 0; mi < 2; ++mi)
                ldm_x4(af[mi][0], af[mi][1], af[mi][2], af[mi][3], aoffs[mi] + ak + cb);
            #pragma unroll
            for (int p = 0; p < 2; ++p) {
                uint32_t r0, r1, r2, r3;
                ldm_x4(r0, r1, r2, r3, boffs[p] + bk + cb);
                uint32_t bf[2][2] = {{r0, r2}, {r1, r3}};
                #pragma unroll
                for (int mi = 0; mi < 2; ++mi)
                    #pragma unroll
                    for (int nj = 0; nj < 2; ++nj)
                        mma16816(acc[mi][2 * p + nj], af[mi], bf[nj]);
            }
        }
    }

    const int g = lane >> 2, q = lane & 3;
    #pragma unroll
    for (int mi = 0; mi < 2; ++mi)
        #pragma unroll
        for (int h = 0; h < 2; ++h) {
            int co = co0 + mi * 16 + g + h * 8;
            float bv = conv_b[co];
            #pragma unroll
            for (int ni = 0; ni < 4; ++ni) {
                int s = s0 + ni * 8 + q * 2;
                float v0 = acc[mi][ni][2 * h]     + bv;
                float v1 = acc[mi][ni][2 * h + 1] + bv;
                v0 = fmaxf(v0, SLOPE * v0);
                v1 = fmaxf(v1, SLOPE * v1);
                *(float2*)(out + (size_t)(b * Cn + co) * Tn + t0 + s) = make_float2(v0, v1);
            }
        }
}

// ---- launch ----
extern "C" void kernel_launch(void* const* d_in, const int* in_sizes, int n_in,
                              void* d_out, int out_size) {
    const float* x      = (const float*)d_in[0];
    const float* weight = (const float*)d_in[1];
    const float* bias   = (const float*)d_in[2];
    const float* conv_v = (const float*)d_in[3];
    const float* conv_g = (const float*)d_in[4];
    const float* conv_b = (const float*)d_in[5];

    __half *gh_ptr, *gx_ptr, *pA, *pA2;
    cudaGetSymbolAddress((void**)&gh_ptr, g_h);
    cudaGetSymbolAddress((void**)&gx_ptr, gX);
    cudaGetSymbolAddress((void**)&pA, gA);
    cudaGetSymbolAddress((void**)&pA2, gA2);

    cudaFuncSetAttribute((const void*)lvc_kernel,
                         cudaFuncAttributeMaxDynamicSharedMemorySize, SMEM_LVC);
    cudaFuncSetAttribute((const void*)dconv_kernel,
                         cudaFuncAttributeMaxDynamicSharedMemorySize, SMEM_DCV);

    wn_prep_kernel<<<1, Cn>>>(conv_v, conv_g);
    xprep_kernel<<<dim3(Tn / 32, Bn), 512>>>(x, gx_ptr);
    transpose_w_kernel<<<dim3(Ln / 32, Cn / 64, Bn * Cn * 3), dim3(512)>>>(weight);
    lvc_kernel<<<Bn * 128, NT, SMEM_LVC>>>(gx_ptr, pA, bias, gh_ptr);
    dconv_kernel<<<Bn * 128, NT, SMEM_DCV>>>(gh_ptr, pA2, conv_b, (float*)d_out);
}

// round 15
// speedup vs baseline: 1.2342x; 1.2342x over previous
#include <cuda_runtime.h>
#include <cuda_fp16.h>
#include <cstdint>

constexpr int Bn = 8, Cn = 128, Tn = 32768, Ln = 256;
constexpr float SLOPE = 0.2f;
constexpr int NT = 1024;

// ---- device scratch ----
__device__ __half gA  [(size_t)Bn * Ln * 3 * Cn * Cn];  // lvc weight [b][l][k][co][ci] fp16
__device__ __half g_h [(size_t)Bn * Cn * Tn];           // LVC output fp16, layout [b][t][co]
__device__ __half gX  [(size_t)Bn * Tn * Cn];           // x fp16, layout [b][t][ci]
__device__ __half gA2 [3 * Cn * Cn];                    // dconv weight [k][co][ci] fp16

// ---- helpers ----
static __device__ __forceinline__ uint32_t smem_u32(const void* p) {
    uint32_t a;
    asm("{ .reg .u64 t; cvta.to.shared.u64 t, %1; cvt.u32.u64 %0, t; }" : "=r"(a) : "l"(p));
    return a;
}
static __device__ __forceinline__ void ldm_x4(uint32_t &r0, uint32_t &r1,
                                              uint32_t &r2, uint32_t &r3, uint32_t addr) {
    asm volatile("ldmatrix.sync.aligned.m8n8.x4.shared.b16 {%0,%1,%2,%3}, [%4];"
                 : "=r"(r0), "=r"(r1), "=r"(r2), "=r"(r3) : "r"(addr));
}
static __device__ __forceinline__ void mma16816(float* c, const uint32_t* a, const uint32_t* b) {
    asm volatile("mma.sync.aligned.m16n8k16.row.col.f32.f16.f16.f32 "
                 "{%0,%1,%2,%3}, {%4,%5,%6,%7}, {%8,%9}, {%0,%1,%2,%3};"
                 : "+f"(c[0]), "+f"(c[1]), "+f"(c[2]), "+f"(c[3])
                 : "r"(a[0]), "r"(a[1]), "r"(a[2]), "r"(a[3]), "r"(b[0]), "r"(b[1]));
}
static __device__ __forceinline__ void cpasync16(uint32_t s, const void* g) {
    asm volatile("cp.async.cg.shared.global [%0], [%1], 16;" :: "r"(s), "l"(g));
}
static __device__ __forceinline__ void cp_commit() {
    asm volatile("cp.async.commit_group;" ::: "memory");
}
static __device__ __forceinline__ void cp_wait0() {
    asm volatile("cp.async.wait_group 0;" ::: "memory");
}
static __device__ __forceinline__ void cp_wait1() {
    asm volatile("cp.async.wait_group 1;" ::: "memory");
}

constexpr uint32_t ATILE = 34816u;          // 128 rows x 272B (one k-tile)

// ---- lvc smem: xT [0, 70176) (258 x 272B); A double-buffer at ABUF; EP at EPOFF ----
constexpr uint32_t ABUF  = 70400u;
constexpr uint32_t EPOFF = ABUF + 2u * ATILE;       // 140032
constexpr uint32_t SMEM_LVC = EPOFF + ATILE;        // 174848

// ---- dconv smem: xT [0, 71264) (262 rows x 272B); A at DSOFF ----
constexpr uint32_t DSOFF = 71264u;
constexpr uint32_t SMEM_DCV = DSOFF + 3u * ATILE;   // 175712

// ---- prep: weight-norm conv weight -> fp16 [k][co][ci] ----
__global__ void wn_prep_kernel(const float* __restrict__ conv_v,
                               const float* __restrict__ conv_g) {
    __shared__ float sc[Cn];
    int co = threadIdx.x;
    float s = 0.f;
    for (int i = 0; i < Cn * 3; ++i) {
        float t = conv_v[co * (Cn * 3) + i];
        s += t * t;
    }
    sc[co] = conv_g[co] / sqrtf(s);
    __syncthreads();
    for (int i = threadIdx.x; i < 3 * Cn * Cn; i += Cn) {
        int k = i >> 14, rest = i & 16383, c2 = rest >> 7, ci = rest & 127;
        gA2[i] = __float2half_rn(conv_v[(c2 * Cn + ci) * 3 + k] * sc[c2]);
    }
}

// ---- transpose W[b][ci][co][k][l] -> gA[b][l][k][co][ci] fp16 ----
// One block per (co, k, b); 4 chunks of 128ci x 64l through stride-65 fp32 tile.
__global__ __launch_bounds__(512)
void transpose_w_kernel(const float* __restrict__ W) {
    __shared__ float tile[128 * 65];
    const int co = blockIdx.x, k = blockIdx.y, b = blockIdx.z;
    const int tid = threadIdx.x;
    const int ci = tid >> 2, l4 = (tid & 3) * 4;
    const float* src0 = W + ((size_t)(b * Cn + ci) * Cn + co) * (3 * Ln)
                          + (size_t)k * Ln + l4;

    #pragma unroll
    for (int l0 = 0; l0 < Ln; l0 += 64) {
        // load 128ci x 64l: 4 independent LDG.128 per thread
        float4 v[4];
        #pragma unroll
        for (int j = 0; j < 4; ++j)
            v[j] = *(const float4*)(src0 + l0 + 16 * j);
        #pragma unroll
        for (int j = 0; j < 4; ++j) {
            float* d = &tile[ci * 65 + l4 + 16 * j];
            d[0] = v[j].x; d[1] = v[j].y; d[2] = v[j].z; d[3] = v[j].w;
        }
        __syncthreads();
        // write 64 l-rows of 128 ci (256B contiguous per row, uint4 per thread)
        #pragma unroll
        for (int jj = 0; jj < 2; ++jj) {
            int j = tid + jj * 512;
            int lr = j >> 4, cg = (j & 15) * 8;
            uint32_t w[4];
            #pragma unroll
            for (int q = 0; q < 4; ++q) {
                __half2 h = __floats2half2_rn(tile[(cg + 2 * q) * 65 + lr],
                                              tile[(cg + 2 * q + 1) * 65 + lr]);
                w[q] = *(uint32_t*)&h;
            }
            size_t o = ((((size_t)b * Ln + l0 + lr) * 3 + k) * Cn + co) * Cn + cg;
            *(uint4*)(gA + o) = *(uint4*)w;
        }
        __syncthreads();
    }
}

// ---- xprep: x fp32 [b][ci][t] -> gX fp16 [b][t][ci] (same tile scheme) ----
__global__ __launch_bounds__(512)
void xprep_kernel(const float* __restrict__ x, __half* __restrict__ xT) {
    __shared__ float tile[128 * 65];
    const int b = blockIdx.y;
    const int tb = blockIdx.x * 256;
    const int tid = threadIdx.x;
    const int ci = tid >> 2, l4 = (tid & 3) * 4;
    const float* src0 = x + (size_t)(b * Cn + ci) * Tn + tb + l4;

    #pragma unroll
    for (int t0 = 0; t0 < 256; t0 += 64) {
        float4 v[4];
        #pragma unroll
        for (int j = 0; j < 4; ++j)
            v[j] = *(const float4*)(src0 + t0 + 16 * j);
        #pragma unroll
        for (int j = 0; j < 4; ++j) {
            float* d = &tile[ci * 65 + l4 + 16 * j];
            d[0] = v[j].x; d[1] = v[j].y; d[2] = v[j].z; d[3] = v[j].w;
        }
        __syncthreads();
        #pragma unroll
        for (int jj = 0; jj < 2; ++jj) {
            int j = tid + jj * 512;
            int tr = j >> 4, cg = (j & 15) * 8;
            uint32_t w[4];
            #pragma unroll
            for (int q = 0; q < 4; ++q) {
                __half2 h = __floats2half2_rn(tile[(cg + 2 * q) * 65 + tr],
                                              tile[(cg + 2 * q + 1) * 65 + tr]);
                w[q] = *(uint32_t*)&h;
            }
            *(uint4*)(xT + ((size_t)b * Tn + tb + t0 + tr) * Cn + cg) = *(uint4*)w;
        }
        __syncthreads();
    }
}

// ---- LVC: 256-wide CTA, cp.async window + 2-deep k-pipeline, transposed epilogue ----
__global__ __launch_bounds__(NT, 1)
void lvc_kernel(const __half* __restrict__ xTsrc, const __half* __restrict__ Aw,
                const float* __restrict__ bias, __half* __restrict__ dstT) {
    extern __shared__ char sm[];
    const uint32_t smb = smem_u32(sm);
    const int tid = threadIdx.x;
    const int b = blockIdx.x >> 7, tt = blockIdx.x & 127;
    const int t0 = tt * 256;

    // window: xT rows c in [0,258), t = t0 - 1 + c — direct cp.async of gX rows
    for (int i = tid; i < 258 * 16; i += NT) {
        int row = i >> 4, chunk = i & 15;
        int t = t0 - 1 + row;
        uint32_t d = smb + (uint32_t)row * 272u + (uint32_t)chunk * 16u;
        if (t >= 0 && t < Tn)
            cpasync16(d, xTsrc + ((size_t)b * Tn + t) * 128 + chunk * 8);
        else
            *(uint4*)(sm + (uint32_t)row * 272u + (uint32_t)chunk * 16u) =
                make_uint4(0, 0, 0, 0);
    }
    cp_commit();

    auto stage_kt = [&](int kt) {
        int p = kt / 3, k = kt - 3 * p;
        const uint4* sA = (const uint4*)(Aw +
            ((size_t)(b * Ln + tt * 2 + p) * 3 + k) * 16384);
        uint32_t buf = smb + ABUF + (uint32_t)(kt & 1) * ATILE;
        #pragma unroll
        for (int j = 0; j < 2; ++j) {
            int i = tid + j * NT;
            int co = i >> 4, c8 = (i & 15) << 3;
            cpasync16(buf + (uint32_t)co * 272u + (uint32_t)c8 * 2u, sA + i);
        }
        cp_commit();
    };
    stage_kt(0);
    stage_kt(1);

    const int warp = tid >> 5, lane = tid & 31;
    const int co0 = (warp >> 3) * 32, s0 = (warp & 7) * 16;
    const uint32_t lrow = lane & 15, lcol = (uint32_t)(lane >> 4) << 4;
    const int g = lane >> 2, q = lane & 3;
    const uint32_t arow = (uint32_t)(co0 + (int)lrow) * 272u + lcol;
    __half* ep = (__half*)(sm + EPOFF);

    #pragma unroll
    for (int p = 0; p < 2; ++p) {
        float acc[2][2][4];
        #pragma unroll
        for (int mi = 0; mi < 2; ++mi)
            #pragma unroll
            for (int ni = 0; ni < 2; ++ni)
                #pragma unroll
                for (int qq = 0; qq < 4; ++qq) acc[mi][ni][qq] = 0.f;

        #pragma unroll
        for (int k = 0; k < 3; ++k) {
            const int kt = 3 * p + k;
            if (kt == 5) cp_wait0(); else cp_wait1();
            __syncthreads();

            const uint32_t abase = smb + ABUF + (uint32_t)(kt & 1) * ATILE + arow;
            const uint32_t bbase = smb + (uint32_t)(p * 128 + k + s0 + (int)lrow) * 272u + lcol;
            #pragma unroll
            for (int ch = 0; ch < 8; ++ch) {
                const uint32_t cb = (uint32_t)ch * 32u;
                uint32_t af[2][4];
                #pragma unroll
                for (int mi = 0; mi < 2; ++mi)
                    ldm_x4(af[mi][0], af[mi][1], af[mi][2], af[mi][3],
                           abase + (uint32_t)(mi * 16) * 272u + cb);
                uint32_t r0, r1, r2, r3;
                ldm_x4(r0, r1, r2, r3, bbase + cb);
                uint32_t bf[2][2] = {{r0, r2}, {r1, r3}};
                #pragma unroll
                for (int mi = 0; mi < 2; ++mi)
                    #pragma unroll
                    for (int ni = 0; ni < 2; ++ni)
                        mma16816(acc[mi][ni], af[mi], bf[ni]);
            }
            __syncthreads();
            if (kt < 4) stage_kt(kt + 2);
        }

        // epilogue: bias + leaky -> EP smem [s][co] -> coalesced rows of g_hT
        const int l = tt * 2 + p;
        #pragma unroll
        for (int mi = 0; mi < 2; ++mi)
            #pragma unroll
            for (int h = 0; h < 2; ++h) {
                int co = co0 + mi * 16 + g + h * 8;
                float bv = bias[(size_t)(b * Cn + co) * Ln + l];
                #pragma unroll
                for (int ni = 0; ni < 2; ++ni) {
                    int s = s0 + ni * 8 + q * 2;
                    float v0 = acc[mi][ni][2 * h]     + bv;
                    float v1 = acc[mi][ni][2 * h + 1] + bv;
                    v0 = fmaxf(v0, SLOPE * v0);
                    v1 = fmaxf(v1, SLOPE * v1);
                    ep[(uint32_t)s * 136u + (uint32_t)co]       = __float2half_rn(v0);
                    ep[(uint32_t)(s + 1) * 136u + (uint32_t)co] = __float2half_rn(v1);
                }
            }
        __syncthreads();
        {
            __half* dbase = dstT + ((size_t)b * Tn + t0 + p * 128) * 128;
            #pragma unroll
            for (int j = 0; j < 2; ++j) {
                int i = tid + j * NT;
                int row = i >> 4, chunk = i & 15;
                uint4 v = *(uint4*)(sm + EPOFF + (uint32_t)row * 272u + (uint32_t)chunk * 16u);
                *(uint4*)(dbase + (size_t)row * 128 + chunk * 8) = v;
            }
        }
    }
}

// ---- dconv: 256-wide, 32x32 warp tiles, pure-cp.async window ----
__global__ __launch_bounds__(NT, 1)
void dconv_kernel(const __half* __restrict__ srcT, const __half* __restrict__ Aw,
                  const float* __restrict__ conv_b, float* __restrict__ out) {
    extern __shared__ char sm[];
    const uint32_t smb = smem_u32(sm);
    const int tid = threadIdx.x;
    const int b = blockIdx.x >> 7, tt = blockIdx.x & 127;
    const int t0 = tt * 256;

    for (int i = tid; i < 262 * 16; i += NT) {
        int row = i >> 4, chunk = i & 15;
        int t = t0 - 3 + row;
        uint32_t d = smb + (uint32_t)row * 272u + (uint32_t)chunk * 16u;
        if (t >= 0 && t < Tn)
            cpasync16(d, srcT + ((size_t)b * Tn + t) * 128 + chunk * 8);
        else
            *(uint4*)(sm + (uint32_t)row * 272u + (uint32_t)chunk * 16u) =
                make_uint4(0, 0, 0, 0);
    }
    {
        const uint4* sA = (const uint4*)Aw;
        #pragma unroll
        for (int j = 0; j < 6; ++j) {
            int i = tid + j * NT;
            int k = i >> 11, r = i & 2047;
            int co = r >> 4, c8 = (r & 15) << 3;
            cpasync16(smb + DSOFF + (uint32_t)k * ATILE
                      + (uint32_t)co * 272u + (uint32_t)c8 * 2u, sA + i);
        }
    }
    cp_commit();
    cp_wait0();
    __syncthreads();

    const int warp = tid >> 5, lane = tid & 31;
    const int co0 = (warp >> 3) * 32, s0 = (warp & 7) * 32;
    const uint32_t lrow = lane & 15, lcol = (uint32_t)(lane >> 4) << 4;

    uint32_t aoffs[2], boffs[2];
    #pragma unroll
    for (int mi = 0; mi < 2; ++mi)
        aoffs[mi] = smb + DSOFF + (uint32_t)(co0 + mi * 16 + (int)lrow) * 272u + lcol;
    #pragma unroll
    for (int p = 0; p < 2; ++p)
        boffs[p] = smb + (uint32_t)(s0 + p * 16 + (int)lrow) * 272u + lcol;

    float acc[2][4][4];
    #pragma unroll
    for (int mi = 0; mi < 2; ++mi)
        #pragma unroll
        for (int ni = 0; ni < 4; ++ni)
            #pragma unroll
            for (int q = 0; q < 4; ++q) acc[mi][ni][q] = 0.f;

    #pragma unroll
    for (int k = 0; k < 3; ++k) {
        const uint32_t ak = (uint32_t)k * ATILE;
        const uint32_t bk = (uint32_t)(3 * k) * 272u;
        #pragma unroll
        for (int ch = 0; ch < 8; ++ch) {
            const uint32_t cb = (uint32_t)ch * 32u;
            uint32_t af[2][4];
            #pragma unroll
            for (int mi = 0; mi < 2; ++mi)
                ldm_x4(af[mi][0], af[mi][1], af[mi][2], af[mi][3], aoffs[mi] + ak + cb);
            #pragma unroll
            for (int p = 0; p < 2; ++p) {
                uint32_t r0, r1, r2, r3;
                ldm_x4(r0, r1, r2, r3, boffs[p] + bk + cb);
                uint32_t bf[2][2] = {{r0, r2}, {r1, r3}};
                #pragma unroll
                for (int mi = 0; mi < 2; ++mi)
                    #pragma unroll
                    for (int nj = 0; nj < 2; ++nj)
                        mma16816(acc[mi][2 * p + nj], af[mi], bf[nj]);
            }
        }
    }

    const int g = lane >> 2, q = lane & 3;
    #pragma unroll
    for (int mi = 0; mi < 2; ++mi)
        #pragma unroll
        for (int h = 0; h < 2; ++h) {
            int co = co0 + mi * 16 + g + h * 8;
            float bv = conv_b[co];
            #pragma unroll
            for (int ni = 0; ni < 4; ++ni) {
                int s = s0 + ni * 8 + q * 2;
                float v0 = acc[mi][ni][2 * h]     + bv;
                float v1 = acc[mi][ni][2 * h + 1] + bv;
                v0 = fmaxf(v0, SLOPE * v0);
                v1 = fmaxf(v1, SLOPE * v1);
                *(float2*)(out + (size_t)(b * Cn + co) * Tn + t0 + s) = make_float2(v0, v1);
            }
        }
}

// ---- launch ----
extern "C" void kernel_launch(void* const* d_in, const int* in_sizes, int n_in,
                              void* d_out, int out_size) {
    const float* x      = (const float*)d_in[0];
    const float* weight = (const float*)d_in[1];
    const float* bias   = (const float*)d_in[2];
    const float* conv_v = (const float*)d_in[3];
    const float* conv_g = (const float*)d_in[4];
    const float* conv_b = (const float*)d_in[5];

    __half *gh_ptr, *gx_ptr, *pA, *pA2;
    cudaGetSymbolAddress((void**)&gh_ptr, g_h);
    cudaGetSymbolAddress((void**)&gx_ptr, gX);
    cudaGetSymbolAddress((void**)&pA, gA);
    cudaGetSymbolAddress((void**)&pA2, gA2);

    cudaFuncSetAttribute((const void*)lvc_kernel,
                         cudaFuncAttributeMaxDynamicSharedMemorySize, SMEM_LVC);
    cudaFuncSetAttribute((const void*)dconv_kernel,
                         cudaFuncAttributeMaxDynamicSharedMemorySize, SMEM_DCV);

    wn_prep_kernel<<<1, Cn>>>(conv_v, conv_g);
    xprep_kernel<<<dim3(Tn / 256, Bn), 512>>>(x, gx_ptr);
    transpose_w_kernel<<<dim3(Cn, 3, Bn), 512>>>(weight);
    lvc_kernel<<<Bn * 128, NT, SMEM_LVC>>>(gx_ptr, pA, bias, gh_ptr);
    dconv_kernel<<<Bn * 128, NT, SMEM_DCV>>>(gh_ptr, pA2, conv_b, (float*)d_out);
}

// round 16
// speedup vs baseline: 1.2413x; 1.0057x over previous
#include <cuda_runtime.h>
#include <cuda_fp16.h>
#include <cstdint>

constexpr int Bn = 8, Cn = 128, Tn = 32768, Ln = 256;
constexpr float SLOPE = 0.2f;
constexpr int NT = 1024;

// ---- device scratch ----
__device__ __half gA  [(size_t)Bn * Ln * 3 * Cn * Cn];  // lvc weight [b][l][k][co][ci] fp16
__device__ __half g_h [(size_t)Bn * Cn * Tn];           // LVC output fp16, layout [b][t][co]
__device__ __half gX  [(size_t)Bn * Tn * Cn];           // x fp16, layout [b][t][ci]
__device__ __half gA2 [3 * Cn * Cn];                    // dconv weight [k][co][ci] fp16

// ---- helpers ----
static __device__ __forceinline__ uint32_t smem_u32(const void* p) {
    uint32_t a;
    asm("{ .reg .u64 t; cvta.to.shared.u64 t, %1; cvt.u32.u64 %0, t; }" : "=r"(a) : "l"(p));
    return a;
}
static __device__ __forceinline__ void ldm_x4(uint32_t &r0, uint32_t &r1,
                                              uint32_t &r2, uint32_t &r3, uint32_t addr) {
    asm volatile("ldmatrix.sync.aligned.m8n8.x4.shared.b16 {%0,%1,%2,%3}, [%4];"
                 : "=r"(r0), "=r"(r1), "=r"(r2), "=r"(r3) : "r"(addr));
}
static __device__ __forceinline__ void mma16816(float* c, const uint32_t* a, const uint32_t* b) {
    asm volatile("mma.sync.aligned.m16n8k16.row.col.f32.f16.f16.f32 "
                 "{%0,%1,%2,%3}, {%4,%5,%6,%7}, {%8,%9}, {%0,%1,%2,%3};"
                 : "+f"(c[0]), "+f"(c[1]), "+f"(c[2]), "+f"(c[3])
                 : "r"(a[0]), "r"(a[1]), "r"(a[2]), "r"(a[3]), "r"(b[0]), "r"(b[1]));
}
static __device__ __forceinline__ void cpasync16(uint32_t s, const void* g) {
    asm volatile("cp.async.cg.shared.global [%0], [%1], 16;" :: "r"(s), "l"(g));
}
static __device__ __forceinline__ void cp_commit() {
    asm volatile("cp.async.commit_group;" ::: "memory");
}
static __device__ __forceinline__ void cp_wait0() {
    asm volatile("cp.async.wait_group 0;" ::: "memory");
}
static __device__ __forceinline__ void cp_wait1() {
    asm volatile("cp.async.wait_group 1;" ::: "memory");
}
static __device__ __forceinline__ void cp_wait2() {
    asm volatile("cp.async.wait_group 2;" ::: "memory");
}

constexpr uint32_t ATILE = 34816u;          // 128 rows x 272B (one k-tile)

// ---- lvc smem: xT [0, 70176) (258 x 272B); A 3-slot ring at ABUF; EP at EPOFF ----
constexpr uint32_t ABUF  = 70400u;
constexpr uint32_t EPOFF = ABUF + 3u * ATILE;       // 174848
constexpr uint32_t SMEM_LVC = EPOFF + ATILE;        // 209664

// ---- dconv smem: xT [0, 71264) (262 rows x 272B); A at DSOFF ----
constexpr uint32_t DSOFF = 71264u;
constexpr uint32_t SMEM_DCV = DSOFF + 3u * ATILE;   // 175712

// ---- prep: weight-norm conv weight -> fp16 [k][co][ci] ----
__global__ void wn_prep_kernel(const float* __restrict__ conv_v,
                               const float* __restrict__ conv_g) {
    __shared__ float sc[Cn];
    int co = threadIdx.x;
    float s = 0.f;
    for (int i = 0; i < Cn * 3; ++i) {
        float t = conv_v[co * (Cn * 3) + i];
        s += t * t;
    }
    sc[co] = conv_g[co] / sqrtf(s);
    __syncthreads();
    for (int i = threadIdx.x; i < 3 * Cn * Cn; i += Cn) {
        int k = i >> 14, rest = i & 16383, c2 = rest >> 7, ci = rest & 127;
        gA2[i] = __float2half_rn(conv_v[(c2 * Cn + ci) * 3 + k] * sc[c2]);
    }
}

// ---- transpose W[b][ci][co][k][l] -> gA[b][l][k][co][ci] fp16 ----
// One block per (64-l chunk, co, k, b): no chunk loop, single barrier pair.
__global__ __launch_bounds__(512)
void transpose_w_kernel(const float* __restrict__ W) {
    __shared__ float tile[128 * 65];
    const int l0 = blockIdx.x * 64;
    const int co = blockIdx.y;
    const int z = blockIdx.z;             // b*3 + k
    const int k = z % 3, b = z / 3;
    const int tid = threadIdx.x;
    const int ci = tid >> 2, l4 = (tid & 3) * 4;
    const float* src0 = W + ((size_t)(b * Cn + ci) * Cn + co) * (3 * Ln)
                          + (size_t)k * Ln + l0 + l4;

    // load 128ci x 64l: 4 independent LDG.128 per thread
    float4 v[4];
    #pragma unroll
    for (int j = 0; j < 4; ++j)
        v[j] = *(const float4*)(src0 + 16 * j);
    #pragma unroll
    for (int j = 0; j < 4; ++j) {
        float* d = &tile[ci * 65 + l4 + 16 * j];
        d[0] = v[j].x; d[1] = v[j].y; d[2] = v[j].z; d[3] = v[j].w;
    }
    __syncthreads();
    // write 64 l-rows of 128 ci (256B contiguous per row, uint4 per thread)
    #pragma unroll
    for (int jj = 0; jj < 2; ++jj) {
        int j = tid + jj * 512;
        int lr = j >> 4, cg = (j & 15) * 8;
        uint32_t w[4];
        #pragma unroll
        for (int q = 0; q < 4; ++q) {
            __half2 h = __floats2half2_rn(tile[(cg + 2 * q) * 65 + lr],
                                          tile[(cg + 2 * q + 1) * 65 + lr]);
            w[q] = *(uint32_t*)&h;
        }
        size_t o = ((((size_t)b * Ln + l0 + lr) * 3 + k) * Cn + co) * Cn + cg;
        *(uint4*)(gA + o) = *(uint4*)w;
    }
}

// ---- xprep: x fp32 [b][ci][t] -> gX fp16 [b][t][ci] ----
__global__ __launch_bounds__(512)
void xprep_kernel(const float* __restrict__ x, __half* __restrict__ xT) {
    __shared__ float tile[128 * 65];
    const int b = blockIdx.y;
    const int tb = blockIdx.x * 256;
    const int tid = threadIdx.x;
    const int ci = tid >> 2, l4 = (tid & 3) * 4;
    const float* src0 = x + (size_t)(b * Cn + ci) * Tn + tb + l4;

    #pragma unroll
    for (int t0 = 0; t0 < 256; t0 += 64) {
        float4 v[4];
        #pragma unroll
        for (int j = 0; j < 4; ++j)
            v[j] = *(const float4*)(src0 + t0 + 16 * j);
        #pragma unroll
        for (int j = 0; j < 4; ++j) {
            float* d = &tile[ci * 65 + l4 + 16 * j];
            d[0] = v[j].x; d[1] = v[j].y; d[2] = v[j].z; d[3] = v[j].w;
        }
        __syncthreads();
        #pragma unroll
        for (int jj = 0; jj < 2; ++jj) {
            int j = tid + jj * 512;
            int tr = j >> 4, cg = (j & 15) * 8;
            uint32_t w[4];
            #pragma unroll
            for (int q = 0; q < 4; ++q) {
                __half2 h = __floats2half2_rn(tile[(cg + 2 * q) * 65 + tr],
                                              tile[(cg + 2 * q + 1) * 65 + tr]);
                w[q] = *(uint32_t*)&h;
            }
            *(uint4*)(xT + ((size_t)b * Tn + tb + t0 + tr) * Cn + cg) = *(uint4*)w;
        }
        __syncthreads();
    }
}

// ---- LVC: 256-wide CTA, cp.async window + 3-slot A pipeline, transposed epilogue ----
__global__ __launch_bounds__(NT, 1)
void lvc_kernel(const __half* __restrict__ xTsrc, const __half* __restrict__ Aw,
                const float* __restrict__ bias, __half* __restrict__ dstT) {
    extern __shared__ char sm[];
    const uint32_t smb = smem_u32(sm);
    const int tid = threadIdx.x;
    const int b = blockIdx.x >> 7, tt = blockIdx.x & 127;
    const int t0 = tt * 256;

    // window: xT rows c in [0,258), t = t0 - 1 + c — direct cp.async of gX rows
    for (int i = tid; i < 258 * 16; i += NT) {
        int row = i >> 4, chunk = i & 15;
        int t = t0 - 1 + row;
        uint32_t d = smb + (uint32_t)row * 272u + (uint32_t)chunk * 16u;
        if (t >= 0 && t < Tn)
            cpasync16(d, xTsrc + ((size_t)b * Tn + t) * 128 + chunk * 8);
        else
            *(uint4*)(sm + (uint32_t)row * 272u + (uint32_t)chunk * 16u) =
                make_uint4(0, 0, 0, 0);
    }
    cp_commit();

    auto stage_kt = [&](int kt) {
        int p = kt / 3, k = kt - 3 * p;
        const uint4* sA = (const uint4*)(Aw +
            ((size_t)(b * Ln + tt * 2 + p) * 3 + k) * 16384);
        uint32_t buf = smb + ABUF + (uint32_t)(kt % 3) * ATILE;
        #pragma unroll
        for (int j = 0; j < 2; ++j) {
            int i = tid + j * NT;
            int co = i >> 4, c8 = (i & 15) << 3;
            cpasync16(buf + (uint32_t)co * 272u + (uint32_t)c8 * 2u, sA + i);
        }
        cp_commit();
    };
    stage_kt(0);
    stage_kt(1);
    stage_kt(2);

    const int warp = tid >> 5, lane = tid & 31;
    const int co0 = (warp >> 3) * 32, s0 = (warp & 7) * 16;
    const uint32_t lrow = lane & 15, lcol = (uint32_t)(lane >> 4) << 4;
    const int g = lane >> 2, q = lane & 3;
    const uint32_t arow = (uint32_t)(co0 + (int)lrow) * 272u + lcol;
    __half* ep = (__half*)(sm + EPOFF);

    #pragma unroll
    for (int p = 0; p < 2; ++p) {
        float acc[2][2][4];
        #pragma unroll
        for (int mi = 0; mi < 2; ++mi)
            #pragma unroll
            for (int ni = 0; ni < 2; ++ni)
                #pragma unroll
                for (int qq = 0; qq < 4; ++qq) acc[mi][ni][qq] = 0.f;

        #pragma unroll
        for (int k = 0; k < 3; ++k) {
            const int kt = 3 * p + k;
            if (kt <= 3) cp_wait2();
            else if (kt == 4) cp_wait1();
            else cp_wait0();
            __syncthreads();

            const uint32_t abase = smb + ABUF + (uint32_t)(kt % 3) * ATILE + arow;
            const uint32_t bbase = smb + (uint32_t)(p * 128 + k + s0 + (int)lrow) * 272u + lcol;
            #pragma unroll
            for (int ch = 0; ch < 8; ++ch) {
                const uint32_t cb = (uint32_t)ch * 32u;
                uint32_t af[2][4];
                #pragma unroll
                for (int mi = 0; mi < 2; ++mi)
                    ldm_x4(af[mi][0], af[mi][1], af[mi][2], af[mi][3],
                           abase + (uint32_t)(mi * 16) * 272u + cb);
                uint32_t r0, r1, r2, r3;
                ldm_x4(r0, r1, r2, r3, bbase + cb);
                uint32_t bf[2][2] = {{r0, r2}, {r1, r3}};
                #pragma unroll
                for (int mi = 0; mi < 2; ++mi)
                    #pragma unroll
                    for (int ni = 0; ni < 2; ++ni)
                        mma16816(acc[mi][ni], af[mi], bf[ni]);
            }
            __syncthreads();
            if (kt < 3) stage_kt(kt + 3);
        }

        // epilogue: bias + leaky -> EP smem [s][co] -> coalesced rows of g_hT
        const int l = tt * 2 + p;
        #pragma unroll
        for (int mi = 0; mi < 2; ++mi)
            #pragma unroll
            for (int h = 0; h < 2; ++h) {
                int co = co0 + mi * 16 + g + h * 8;
                float bv = bias[(size_t)(b * Cn + co) * Ln + l];
                #pragma unroll
                for (int ni = 0; ni < 2; ++ni) {
                    int s = s0 + ni * 8 + q * 2;
                    float v0 = acc[mi][ni][2 * h]     + bv;
                    float v1 = acc[mi][ni][2 * h + 1] + bv;
                    v0 = fmaxf(v0, SLOPE * v0);
                    v1 = fmaxf(v1, SLOPE * v1);
                    ep[(uint32_t)s * 136u + (uint32_t)co]       = __float2half_rn(v0);
                    ep[(uint32_t)(s + 1) * 136u + (uint32_t)co] = __float2half_rn(v1);
                }
            }
        __syncthreads();
        {
            __half* dbase = dstT + ((size_t)b * Tn + t0 + p * 128) * 128;
            #pragma unroll
            for (int j = 0; j < 2; ++j) {
                int i = tid + j * NT;
                int row = i >> 4, chunk = i & 15;
                uint4 v = *(uint4*)(sm + EPOFF + (uint32_t)row * 272u + (uint32_t)chunk * 16u);
                *(uint4*)(dbase + (size_t)row * 128 + chunk * 8) = v;
            }
        }
    }
}

// ---- dconv: 256-wide, 32x32 warp tiles, pure-cp.async window ----
__global__ __launch_bounds__(NT, 1)
void dconv_kernel(const __half* __restrict__ srcT, const __half* __restrict__ Aw,
                  const float* __restrict__ conv_b, float* __restrict__ out) {
    extern __shared__ char sm[];
    const uint32_t smb = smem_u32(sm);
    const int tid = threadIdx.x;
    const int b = blockIdx.x >> 7, tt = blockIdx.x & 127;
    const int t0 = tt * 256;

    for (int i = tid; i < 262 * 16; i += NT) {
        int row = i >> 4, chunk = i & 15;
        int t = t0 - 3 + row;
        uint32_t d = smb + (uint32_t)row * 272u + (uint32_t)chunk * 16u;
        if (t >= 0 && t < Tn)
            cpasync16(d, srcT + ((size_t)b * Tn + t) * 128 + chunk * 8);
        else
            *(uint4*)(sm + (uint32_t)row * 272u + (uint32_t)chunk * 16u) =
                make_uint4(0, 0, 0, 0);
    }
    {
        const uint4* sA = (const uint4*)Aw;
        #pragma unroll
        for (int j = 0; j < 6; ++j) {
            int i = tid + j * NT;
            int k = i >> 11, r = i & 2047;
            int co = r >> 4, c8 = (r & 15) << 3;
            cpasync16(smb + DSOFF + (uint32_t)k * ATILE
                      + (uint32_t)co * 272u + (uint32_t)c8 * 2u, sA + i);
        }
    }
    cp_commit();
    cp_wait0();
    __syncthreads();

    const int warp = tid >> 5, lane = tid & 31;
    const int co0 = (warp >> 3) * 32, s0 = (warp & 7) * 32;
    const uint32_t lrow = lane & 15, lcol = (uint32_t)(lane >> 4) << 4;

    uint32_t aoffs[2], boffs[2];
    #pragma unroll
    for (int mi = 0; mi < 2; ++mi)
        aoffs[mi] = smb + DSOFF + (uint32_t)(co0 + mi * 16 + (int)lrow) * 272u + lcol;
    #pragma unroll
    for (int p = 0; p < 2; ++p)
        boffs[p] = smb + (uint32_t)(s0 + p * 16 + (int)lrow) * 272u + lcol;

    float acc[2][4][4];
    #pragma unroll
    for (int mi = 0; mi < 2; ++mi)
        #pragma unroll
        for (int ni = 0; ni < 4; ++ni)
            #pragma unroll
            for (int q = 0; q < 4; ++q) acc[mi][ni][q] = 0.f;

    #pragma unroll
    for (int k = 0; k < 3; ++k) {
        const uint32_t ak = (uint32_t)k * ATILE;
        const uint32_t bk = (uint32_t)(3 * k) * 272u;
        #pragma unroll
        for (int ch = 0; ch < 8; ++ch) {
            const uint32_t cb = (uint32_t)ch * 32u;
            uint32_t af[2][4];
            #pragma unroll
            for (int mi = 0; mi < 2; ++mi)
                ldm_x4(af[mi][0], af[mi][1], af[mi][2], af[mi][3], aoffs[mi] + ak + cb);
            #pragma unroll
            for (int p = 0; p < 2; ++p) {
                uint32_t r0, r1, r2, r3;
                ldm_x4(r0, r1, r2, r3, boffs[p] + bk + cb);
                uint32_t bf[2][2] = {{r0, r2}, {r1, r3}};
                #pragma unroll
                for (int mi = 0; mi < 2; ++mi)
                    #pragma unroll
                    for (int nj = 0; nj < 2; ++nj)
                        mma16816(acc[mi][2 * p + nj], af[mi], bf[nj]);
            }
        }
    }

    const int g = lane >> 2, q = lane & 3;
    #pragma unroll
    for (int mi = 0; mi < 2; ++mi)
        #pragma unroll
        for (int h = 0; h < 2; ++h) {
            int co = co0 + mi * 16 + g + h * 8;
            float bv = conv_b[co];
            #pragma unroll
            for (int ni = 0; ni < 4; ++ni) {
                int s = s0 + ni * 8 + q * 2;
                float v0 = acc[mi][ni][2 * h]     + bv;
                float v1 = acc[mi][ni][2 * h + 1] + bv;
                v0 = fmaxf(v0, SLOPE * v0);
                v1 = fmaxf(v1, SLOPE * v1);
                *(float2*)(out + (size_t)(b * Cn + co) * Tn + t0 + s) = make_float2(v0, v1);
            }
        }
}

// ---- launch ----
extern "C" void kernel_launch(void* const* d_in, const int* in_sizes, int n_in,
                              void* d_out, int out_size) {
    const float* x      = (const float*)d_in[0];
    const float* weight = (const float*)d_in[1];
    const float* bias   = (const float*)d_in[2];
    const float* conv_v = (const float*)d_in[3];
    const float* conv_g = (const float*)d_in[4];
    const float* conv_b = (const float*)d_in[5];

    __half *gh_ptr, *gx_ptr, *pA, *pA2;
    cudaGetSymbolAddress((void**)&gh_ptr, g_h);
    cudaGetSymbolAddress((void**)&gx_ptr, gX);
    cudaGetSymbolAddress((void**)&pA, gA);
    cudaGetSymbolAddress((void**)&pA2, gA2);

    cudaFuncSetAttribute((const void*)lvc_kernel,
                         cudaFuncAttributeMaxDynamicSharedMemorySize, SMEM_LVC);
    cudaFuncSetAttribute((const void*)dconv_kernel,
                         cudaFuncAttributeMaxDynamicSharedMemorySize, SMEM_DCV);

    wn_prep_kernel<<<1, Cn>>>(conv_v, conv_g);
    xprep_kernel<<<dim3(Tn / 256, Bn), 512>>>(x, gx_ptr);
    transpose_w_kernel<<<dim3(Ln / 64, Cn, 3 * Bn), 512>>>(weight);
    lvc_kernel<<<Bn * 128, NT, SMEM_LVC>>>(gx_ptr, pA, bias, gh_ptr);
    dconv_kernel<<<Bn * 128, NT, SMEM_DCV>>>(gh_ptr, pA2, conv_b, (float*)d_out);
}

// round 17
// speedup vs baseline: 1.2850x; 1.0352x over previous
#include <cuda_runtime.h>
#include <cuda_fp16.h>
#include <cstdint>

constexpr int Bn = 8, Cn = 128, Tn = 32768, Ln = 256;
constexpr float SLOPE = 0.2f;
constexpr int NT = 1024;

// ---- device scratch ----
__device__ __half gA  [(size_t)Bn * Ln * 3 * Cn * Cn];  // lvc weight [b][l][k][co][ci] fp16
__device__ __half g_h [(size_t)Bn * Cn * Tn];           // LVC output fp16, layout [b][t][co]
__device__ __half gX  [(size_t)Bn * Tn * Cn];           // x fp16, layout [b][t][ci]
__device__ __half gA2 [3 * Cn * Cn];                    // dconv weight [k][co][ci] fp16

// ---- helpers ----
static __device__ __forceinline__ uint32_t smem_u32(const void* p) {
    uint32_t a;
    asm("{ .reg .u64 t; cvta.to.shared.u64 t, %1; cvt.u32.u64 %0, t; }" : "=r"(a) : "l"(p));
    return a;
}
static __device__ __forceinline__ void ldm_x4(uint32_t &r0, uint32_t &r1,
                                              uint32_t &r2, uint32_t &r3, uint32_t addr) {
    asm volatile("ldmatrix.sync.aligned.m8n8.x4.shared.b16 {%0,%1,%2,%3}, [%4];"
                 : "=r"(r0), "=r"(r1), "=r"(r2), "=r"(r3) : "r"(addr));
}
static __device__ __forceinline__ void mma16816(float* c, const uint32_t* a, const uint32_t* b) {
    asm volatile("mma.sync.aligned.m16n8k16.row.col.f32.f16.f16.f32 "
                 "{%0,%1,%2,%3}, {%4,%5,%6,%7}, {%8,%9}, {%0,%1,%2,%3};"
                 : "+f"(c[0]), "+f"(c[1]), "+f"(c[2]), "+f"(c[3])
                 : "r"(a[0]), "r"(a[1]), "r"(a[2]), "r"(a[3]), "r"(b[0]), "r"(b[1]));
}
static __device__ __forceinline__ void cpasync16(uint32_t s, const void* g) {
    asm volatile("cp.async.cg.shared.global [%0], [%1], 16;" :: "r"(s), "l"(g));
}
static __device__ __forceinline__ void cp_commit() {
    asm volatile("cp.async.commit_group;" ::: "memory");
}
static __device__ __forceinline__ void cp_wait0() {
    asm volatile("cp.async.wait_group 0;" ::: "memory");
}
static __device__ __forceinline__ void cp_wait1() {
    asm volatile("cp.async.wait_group 1;" ::: "memory");
}

constexpr uint32_t ATILE = 34816u;          // 128 rows x 272B (one k-tile, one l)

// ---- lvc smem: window [0, 70176) (258 x 272B); 4 A slots (2 l-pairs) at ABUF;
//      EP bounce overlays slots 0-1 after the mainloop ----
constexpr uint32_t ABUF  = 70400u;
constexpr uint32_t SMEM_LVC = ABUF + 4u * ATILE;    // 209664

// ---- dconv smem: xT [0, 71264) (262 rows x 272B); A at DSOFF ----
constexpr uint32_t DSOFF = 71264u;
constexpr uint32_t SMEM_DCV = DSOFF + 3u * ATILE;   // 175712

// ---- prep: weight-norm conv weight -> fp16 [k][co][ci] ----
__global__ void wn_prep_kernel(const float* __restrict__ conv_v,
                               const float* __restrict__ conv_g) {
    __shared__ float sc[Cn];
    int co = threadIdx.x;
    float s = 0.f;
    for (int i = 0; i < Cn * 3; ++i) {
        float t = conv_v[co * (Cn * 3) + i];
        s += t * t;
    }
    sc[co] = conv_g[co] / sqrtf(s);
    __syncthreads();
    for (int i = threadIdx.x; i < 3 * Cn * Cn; i += Cn) {
        int k = i >> 14, rest = i & 16383, c2 = rest >> 7, ci = rest & 127;
        gA2[i] = __float2half_rn(conv_v[(c2 * Cn + ci) * 3 + k] * sc[c2]);
    }
}

// ---- transpose W[b][ci][co][k][l] -> gA[b][l][k][co][ci] fp16 ----
__global__ __launch_bounds__(512)
void transpose_w_kernel(const float* __restrict__ W) {
    __shared__ float tile[128 * 65];
    const int l0 = blockIdx.x * 64;
    const int co = blockIdx.y;
    const int z = blockIdx.z;             // b*3 + k
    const int k = z % 3, b = z / 3;
    const int tid = threadIdx.x;
    const int ci = tid >> 2, l4 = (tid & 3) * 4;
    const float* src0 = W + ((size_t)(b * Cn + ci) * Cn + co) * (3 * Ln)
                          + (size_t)k * Ln + l0 + l4;

    float4 v[4];
    #pragma unroll
    for (int j = 0; j < 4; ++j)
        v[j] = *(const float4*)(src0 + 16 * j);
    #pragma unroll
    for (int j = 0; j < 4; ++j) {
        float* d = &tile[ci * 65 + l4 + 16 * j];
        d[0] = v[j].x; d[1] = v[j].y; d[2] = v[j].z; d[3] = v[j].w;
    }
    __syncthreads();
    #pragma unroll
    for (int jj = 0; jj < 2; ++jj) {
        int j = tid + jj * 512;
        int lr = j >> 4, cg = (j & 15) * 8;
        uint32_t w[4];
        #pragma unroll
        for (int q = 0; q < 4; ++q) {
            __half2 h = __floats2half2_rn(tile[(cg + 2 * q) * 65 + lr],
                                          tile[(cg + 2 * q + 1) * 65 + lr]);
            w[q] = *(uint32_t*)&h;
        }
        size_t o = ((((size_t)b * Ln + l0 + lr) * 3 + k) * Cn + co) * Cn + cg;
        *(uint4*)(gA + o) = *(uint4*)w;
    }
}

// ---- xprep: x fp32 [b][ci][t] -> gX fp16 [b][t][ci] ----
__global__ __launch_bounds__(512)
void xprep_kernel(const float* __restrict__ x, __half* __restrict__ xT) {
    __shared__ float tile[128 * 65];
    const int b = blockIdx.y;
    const int tb = blockIdx.x * 256;
    const int tid = threadIdx.x;
    const int ci = tid >> 2, l4 = (tid & 3) * 4;
    const float* src0 = x + (size_t)(b * Cn + ci) * Tn + tb + l4;

    #pragma unroll
    for (int t0 = 0; t0 < 256; t0 += 64) {
        float4 v[4];
        #pragma unroll
        for (int j = 0; j < 4; ++j)
            v[j] = *(const float4*)(src0 + t0 + 16 * j);
        #pragma unroll
        for (int j = 0; j < 4; ++j) {
            float* d = &tile[ci * 65 + l4 + 16 * j];
            d[0] = v[j].x; d[1] = v[j].y; d[2] = v[j].z; d[3] = v[j].w;
        }
        __syncthreads();
        #pragma unroll
        for (int jj = 0; jj < 2; ++jj) {
            int j = tid + jj * 512;
            int tr = j >> 4, cg = (j & 15) * 8;
            uint32_t w[4];
            #pragma unroll
            for (int q = 0; q < 4; ++q) {
                __half2 h = __floats2half2_rn(tile[(cg + 2 * q) * 65 + tr],
                                              tile[(cg + 2 * q + 1) * 65 + tr]);
                w[q] = *(uint32_t*)&h;
            }
            *(uint4*)(xT + ((size_t)b * Tn + tb + t0 + tr) * Cn + cg) = *(uint4*)w;
        }
        __syncthreads();
    }
}

// ---- LVC: 256-wide CTA, 32 warps of 32x32 tiles, l-pair A staging ----
__global__ __launch_bounds__(NT, 1)
void lvc_kernel(const __half* __restrict__ xTsrc, const __half* __restrict__ Aw,
                const float* __restrict__ bias, __half* __restrict__ dstT) {
    extern __shared__ char sm[];
    const uint32_t smb = smem_u32(sm);
    const int tid = threadIdx.x;
    const int b = blockIdx.x >> 7, tt = blockIdx.x & 127;
    const int t0 = tt * 256;

    // window: rows c in [0,258), t = t0 - 1 + c — cp.async of gX rows  (group G0)
    for (int i = tid; i < 258 * 16; i += NT) {
        int row = i >> 4, chunk = i & 15;
        int t = t0 - 1 + row;
        uint32_t d = smb + (uint32_t)row * 272u + (uint32_t)chunk * 16u;
        if (t >= 0 && t < Tn)
            cpasync16(d, xTsrc + ((size_t)b * Tn + t) * 128 + chunk * 8);
        else
            *(uint4*)(sm + (uint32_t)row * 272u + (uint32_t)chunk * 16u) =
                make_uint4(0, 0, 0, 0);
    }
    cp_commit();

    // stage (l0,l1) A-pair for k into ring slots {0,1} (even k) / {2,3} (odd k)
    auto stage_pair = [&](int k) {
        #pragma unroll
        for (int l01 = 0; l01 < 2; ++l01) {
            const uint4* sA = (const uint4*)(Aw +
                ((size_t)(b * Ln + tt * 2 + l01) * 3 + k) * 16384);
            uint32_t buf = smb + ABUF + (uint32_t)((k & 1) * 2 + l01) * ATILE;
            #pragma unroll
            for (int j = 0; j < 2; ++j) {
                int i = tid + j * NT;
                int co = i >> 4, c8 = (i & 15) << 3;
                cpasync16(buf + (uint32_t)co * 272u + (uint32_t)c8 * 2u, sA + i);
            }
        }
        cp_commit();
    };
    stage_pair(0);   // G1
    stage_pair(1);   // G2

    const int warp = tid >> 5, lane = tid & 31;
    const int co0 = (warp >> 3) * 32, s0 = (warp & 7) * 32;   // s0 in [0,256)
    const uint32_t lrow = lane & 15, lcol = (uint32_t)(lane >> 4) << 4;
    const uint32_t a_l = (s0 >= 128) ? ATILE : 0u;            // which l's A-tile

    uint32_t aoffs[2], boffs[2];
    #pragma unroll
    for (int mi = 0; mi < 2; ++mi)
        aoffs[mi] = a_l + (uint32_t)(co0 + mi * 16 + (int)lrow) * 272u + lcol;
    #pragma unroll
    for (int p = 0; p < 2; ++p)
        boffs[p] = smb + (uint32_t)(s0 + p * 16 + (int)lrow) * 272u + lcol;

    float acc[2][4][4];
    #pragma unroll
    for (int mi = 0; mi < 2; ++mi)
        #pragma unroll
        for (int ni = 0; ni < 4; ++ni)
            #pragma unroll
            for (int q = 0; q < 4; ++q) acc[mi][ni][q] = 0.f;

    #pragma unroll
    for (int k = 0; k < 3; ++k) {
        if (k < 2) cp_wait1(); else cp_wait0();
        __syncthreads();

        const uint32_t abase = smb + ABUF + (uint32_t)((k & 1) * 2) * ATILE;
        const uint32_t bk = (uint32_t)k * 272u;
        #pragma unroll
        for (int ch = 0; ch < 8; ++ch) {
            const uint32_t cb = (uint32_t)ch * 32u;
            uint32_t af[2][4];
            #pragma unroll
            for (int mi = 0; mi < 2; ++mi)
                ldm_x4(af[mi][0], af[mi][1], af[mi][2], af[mi][3], abase + aoffs[mi] + cb);
            #pragma unroll
            for (int p = 0; p < 2; ++p) {
                uint32_t r0, r1, r2, r3;
                ldm_x4(r0, r1, r2, r3, boffs[p] + bk + cb);
                uint32_t bf[2][2] = {{r0, r2}, {r1, r3}};
                #pragma unroll
                for (int mi = 0; mi < 2; ++mi)
                    #pragma unroll
                    for (int nj = 0; nj < 2; ++nj)
                        mma16816(acc[mi][2 * p + nj], af[mi], bf[nj]);
            }
        }
        __syncthreads();
        if (k == 0) stage_pair(2);   // G3, into slots {0,1} (free after this sync)
    }

    // epilogue: EP bounce overlays A slots 0-1; two 128-row phases
    const int g = lane >> 2, q = lane & 3;
    const int l = tt * 2 + (s0 >> 7);
    __half* ep = (__half*)(sm + ABUF);
    float bv[2][2];
    #pragma unroll
    for (int mi = 0; mi < 2; ++mi)
        #pragma unroll
        for (int h = 0; h < 2; ++h) {
            int co = co0 + mi * 16 + g + h * 8;
            bv[mi][h] = bias[(size_t)(b * Cn + co) * Ln + l];
        }

    #pragma unroll
    for (int ph = 0; ph < 2; ++ph) {
        if ((s0 >> 7) == ph) {
            #pragma unroll
            for (int mi = 0; mi < 2; ++mi)
                #pragma unroll
                for (int h = 0; h < 2; ++h) {
                    int co = co0 + mi * 16 + g + h * 8;
                    #pragma unroll
                    for (int ni = 0; ni < 4; ++ni) {
                        int s = (s0 & 127) + ni * 8 + q * 2;
                        float v0 = acc[mi][ni][2 * h]     + bv[mi][h];
                        float v1 = acc[mi][ni][2 * h + 1] + bv[mi][h];
                        v0 = fmaxf(v0, SLOPE * v0);
                        v1 = fmaxf(v1, SLOPE * v1);
                        ep[(uint32_t)s * 136u + (uint32_t)co]       = __float2half_rn(v0);
                        ep[(uint32_t)(s + 1) * 136u + (uint32_t)co] = __float2half_rn(v1);
                    }
                }
        }
        __syncthreads();
        {
            __half* dbase = dstT + ((size_t)b * Tn + t0 + ph * 128) * 128;
            #pragma unroll
            for (int j = 0; j < 2; ++j) {
                int i = tid + j * NT;
                int row = i >> 4, chunk = i & 15;
                uint4 v = *(uint4*)(sm + ABUF + (uint32_t)row * 272u + (uint32_t)chunk * 16u);
                *(uint4*)(dbase + (size_t)row * 128 + chunk * 8) = v;
            }
        }
        __syncthreads();
    }
}

// ---- dconv: 256-wide, 32x32 warp tiles, pure-cp.async window ----
__global__ __launch_bounds__(NT, 1)
void dconv_kernel(const __half* __restrict__ srcT, const __half* __restrict__ Aw,
                  const float* __restrict__ conv_b, float* __restrict__ out) {
    extern __shared__ char sm[];
    const uint32_t smb = smem_u32(sm);
    const int tid = threadIdx.x;
    const int b = blockIdx.x >> 7, tt = blockIdx.x & 127;
    const int t0 = tt * 256;

    for (int i = tid; i < 262 * 16; i += NT) {
        int row = i >> 4, chunk = i & 15;
        int t = t0 - 3 + row;
        uint32_t d = smb + (uint32_t)row * 272u + (uint32_t)chunk * 16u;
        if (t >= 0 && t < Tn)
            cpasync16(d, srcT + ((size_t)b * Tn + t) * 128 + chunk * 8);
        else
            *(uint4*)(sm + (uint32_t)row * 272u + (uint32_t)chunk * 16u) =
                make_uint4(0, 0, 0, 0);
    }
    {
        const uint4* sA = (const uint4*)Aw;
        #pragma unroll
        for (int j = 0; j < 6; ++j) {
            int i = tid + j * NT;
            int k = i >> 11, r = i & 2047;
            int co = r >> 4, c8 = (r & 15) << 3;
            cpasync16(smb + DSOFF + (uint32_t)k * ATILE
                      + (uint32_t)co * 272u + (uint32_t)c8 * 2u, sA + i);
        }
    }
    cp_commit();
    cp_wait0();
    __syncthreads();

    const int warp = tid >> 5, lane = tid & 31;
    const int co0 = (warp >> 3) * 32, s0 = (warp & 7) * 32;
    const uint32_t lrow = lane & 15, lcol = (uint32_t)(lane >> 4) << 4;

    uint32_t aoffs[2], boffs[2];
    #pragma unroll
    for (int mi = 0; mi < 2; ++mi)
        aoffs[mi] = smb + DSOFF + (uint32_t)(co0 + mi * 16 + (int)lrow) * 272u + lcol;
    #pragma unroll
    for (int p = 0; p < 2; ++p)
        boffs[p] = smb + (uint32_t)(s0 + p * 16 + (int)lrow) * 272u + lcol;

    float acc[2][4][4];
    #pragma unroll
    for (int mi = 0; mi < 2; ++mi)
        #pragma unroll
        for (int ni = 0; ni < 4; ++ni)
            #pragma unroll
            for (int q = 0; q < 4; ++q) acc[mi][ni][q] = 0.f;

    #pragma unroll
    for (int k = 0; k < 3; ++k) {
        const uint32_t ak = (uint32_t)k * ATILE;
        const uint32_t bk = (uint32_t)(3 * k) * 272u;
        #pragma unroll
        for (int ch = 0; ch < 8; ++ch) {
            const uint32_t cb = (uint32_t)ch * 32u;
            uint32_t af[2][4];
            #pragma unroll
            for (int mi = 0; mi < 2; ++mi)
                ldm_x4(af[mi][0], af[mi][1], af[mi][2], af[mi][3], aoffs[mi] + ak + cb);
            #pragma unroll
            for (int p = 0; p < 2; ++p) {
                uint32_t r0, r1, r2, r3;
                ldm_x4(r0, r1, r2, r3, boffs[p] + bk + cb);
                uint32_t bf[2][2] = {{r0, r2}, {r1, r3}};
                #pragma unroll
                for (int mi = 0; mi < 2; ++mi)
                    #pragma unroll
                    for (int nj = 0; nj < 2; ++nj)
                        mma16816(acc[mi][2 * p + nj], af[mi], bf[nj]);
            }
        }
    }

    const int g = lane >> 2, q = lane & 3;
    #pragma unroll
    for (int mi = 0; mi < 2; ++mi)
        #pragma unroll
        for (int h = 0; h < 2; ++h) {
            int co = co0 + mi * 16 + g + h * 8;
            float bv = conv_b[co];
            #pragma unroll
            for (int ni = 0; ni < 4; ++ni) {
                int s = s0 + ni * 8 + q * 2;
                float v0 = acc[mi][ni][2 * h]     + bv;
                float v1 = acc[mi][ni][2 * h + 1] + bv;
                v0 = fmaxf(v0, SLOPE * v0);
                v1 = fmaxf(v1, SLOPE * v1);
                *(float2*)(out + (size_t)(b * Cn + co) * Tn + t0 + s) = make_float2(v0, v1);
            }
        }
}

// ---- launch ----
extern "C" void kernel_launch(void* const* d_in, const int* in_sizes, int n_in,
                              void* d_out, int out_size) {
    const float* x      = (const float*)d_in[0];
    const float* weight = (const float*)d_in[1];
    const float* bias   = (const float*)d_in[2];
    const float* conv_v = (const float*)d_in[3];
    const float* conv_g = (const float*)d_in[4];
    const float* conv_b = (const float*)d_in[5];

    __half *gh_ptr, *gx_ptr, *pA, *pA2;
    cudaGetSymbolAddress((void**)&gh_ptr, g_h);
    cudaGetSymbolAddress((void**)&gx_ptr, gX);
    cudaGetSymbolAddress((void**)&pA, gA);
    cudaGetSymbolAddress((void**)&pA2, gA2);

    cudaFuncSetAttribute((const void*)lvc_kernel,
                         cudaFuncAttributeMaxDynamicSharedMemorySize, SMEM_LVC);
    cudaFuncSetAttribute((const void*)dconv_kernel,
                         cudaFuncAttributeMaxDynamicSharedMemorySize, SMEM_DCV);

    wn_prep_kernel<<<1, Cn>>>(conv_v, conv_g);
    xprep_kernel<<<dim3(Tn / 256, Bn), 512>>>(x, gx_ptr);
    transpose_w_kernel<<<dim3(Ln / 64, Cn, 3 * Bn), 512>>>(weight);
    lvc_kernel<<<Bn * 128, NT, SMEM_LVC>>>(gx_ptr, pA, bias, gh_ptr);
    dconv_kernel<<<Bn * 128, NT, SMEM_DCV>>>(gh_ptr, pA2, conv_b, (float*)d_out);
}